// round 9
// baseline (speedup 1.0000x reference)
#include <cuda_runtime.h>
#include <cuda_bf16.h>
#include <cstdint>
#include <cstddef>

// ---------------- problem constants ----------------
constexpr int NUSER = 100000;
constexpr int NITEM = 50000;
constexpr int NN    = 150000;   // total nodes
constexpr int DD    = 128;
constexpr int BB    = 3;
constexpr int LL    = 2;
constexpr int EE    = 1500000;
constexpr float BN_EPS = 1e-5f;
constexpr int SEGS  = BB * NN;                      // 450000 (b,dst) segments
constexpr int SCAN_BLOCKS = (SEGS + 1023) / 1024;   // 440

// ---------------- device scratch (no allocation allowed) ----------------
__device__ float g_x[(size_t)NN * DD];           // initial node features
__device__ float g_h[(size_t)NN * DD];           // current hidden
__device__ float g_agg[(size_t)NN * DD];         // aggregation scratch
__device__ float g_Q[(size_t)NN * DD];           // attention query
__device__ float g_stack[(size_t)BB * NN * DD];  // per-behavior outputs
__device__ float g_rd[SEGS];                     // 1/max(deg,1)
__device__ float g_logits[(size_t)NN * BB];
__device__ float g_colstat[2 * DD];              // BN column sum / sumsq
__device__ float g_bnsc[DD], g_bnsh[DD];         // BN fused scale / shift
__device__ float g_Wc[DD * DD];                  // fuse_W @ refine_W
__device__ float g_bc[DD];                       // fuse_b @ refine_W + refine_b
__device__ int   g_icnt[SEGS];                   // degree per (b,dst)
__device__ int   g_coff[SEGS];                   // CSR offsets
__device__ int   g_ccur[SEGS];                   // fill cursors
__device__ int   g_bsum[SCAN_BLOCKS + 8];
__device__ int   g_bsumoff[SCAN_BLOCKS + 8];
__device__ int   g_csrc[EE];                     // CSR src lists
// weight images: 20 slots x (hi 16384 + lo 16384) bf16 in plain [k*128+n] layout
__device__ __nv_bfloat16 g_wimg[(size_t)20 * 2 * 16384];

// ---------------- helpers ----------------
__device__ __forceinline__ uint32_t smem_to_u32(const void* p) {
    uint32_t a;
    asm("{ .reg .u64 t; cvta.to.shared.u64 t, %1; cvt.u32.u64 %0, t; }" : "=r"(a) : "l"(p));
    return a;
}

#define LDSM_X4(r0, r1, r2, r3, addr) \
    asm volatile("ldmatrix.sync.aligned.m8n8.x4.shared.b16 {%0,%1,%2,%3}, [%4];" \
        : "=r"(r0), "=r"(r1), "=r"(r2), "=r"(r3) : "r"(addr))
#define LDSM_X4_T(r0, r1, r2, r3, addr) \
    asm volatile("ldmatrix.sync.aligned.m8n8.x4.trans.shared.b16 {%0,%1,%2,%3}, [%4];" \
        : "=r"(r0), "=r"(r1), "=r"(r2), "=r"(r3) : "r"(addr))
#define MMA_BF16(d, a, b) \
    asm volatile("mma.sync.aligned.m16n8k16.row.col.f32.bf16.bf16.f32 " \
        "{%0,%1,%2,%3}, {%4,%5,%6,%7}, {%8,%9}, {%0,%1,%2,%3};" \
        : "+f"((d)[0]), "+f"((d)[1]), "+f"((d)[2]), "+f"((d)[3]) \
        : "r"((a)[0]), "r"((a)[1]), "r"((a)[2]), "r"((a)[3]), "r"((b)[0]), "r"((b)[1]))

// ---------------- small kernels ----------------
__global__ void zero_int_kernel(int4* p, int n4) {
    int i = blockIdx.x * blockDim.x + threadIdx.x;
    int stride = gridDim.x * blockDim.x;
    int4 z = make_int4(0, 0, 0, 0);
    for (; i < n4; i += stride) p[i] = z;
}

__global__ void zero_stats_kernel() {
    if (threadIdx.x < 2 * DD) g_colstat[threadIdx.x] = 0.f;
}

__global__ void count_kernel(const int* __restrict__ ei, const int* __restrict__ et) {
    int e = blockIdx.x * blockDim.x + threadIdx.x;
    if (e >= EE) return;
    atomicAdd(&g_icnt[et[e] * NN + ei[EE + e]], 1);
}

__global__ void scan1_kernel() {
    __shared__ int s[1024];
    int gid = blockIdx.x * 1024 + threadIdx.x;
    int v = (gid < SEGS) ? g_icnt[gid] : 0;
    s[threadIdx.x] = v;
    __syncthreads();
#pragma unroll
    for (int off = 1; off < 1024; off <<= 1) {
        int t = (threadIdx.x >= off) ? s[threadIdx.x - off] : 0;
        __syncthreads();
        s[threadIdx.x] += t;
        __syncthreads();
    }
    if (gid < SEGS) g_coff[gid] = s[threadIdx.x] - v;
    if (threadIdx.x == 1023) g_bsum[blockIdx.x] = s[1023];
}

__global__ void scan2_kernel() {
    __shared__ int s[512];
    int t = threadIdx.x;
    int v = (t < SCAN_BLOCKS) ? g_bsum[t] : 0;
    s[t] = v;
    __syncthreads();
#pragma unroll
    for (int off = 1; off < 512; off <<= 1) {
        int x = (t >= off) ? s[t - off] : 0;
        __syncthreads();
        s[t] += x;
        __syncthreads();
    }
    if (t < SCAN_BLOCKS) g_bsumoff[t] = s[t] - v;
}

__global__ void scan3_kernel() {
    int gid = blockIdx.x * 1024 + threadIdx.x;
    if (gid >= SEGS) return;
    int o = g_coff[gid] + g_bsumoff[gid >> 10];
    g_coff[gid] = o;
    g_ccur[gid] = o;
    g_rd[gid] = 1.0f / fmaxf((float)g_icnt[gid], 1.0f);
}

__global__ void fill_kernel(const int* __restrict__ ei, const int* __restrict__ et) {
    int e = blockIdx.x * blockDim.x + threadIdx.x;
    if (e >= EE) return;
    int pos = atomicAdd(&g_ccur[et[e] * NN + ei[EE + e]], 1);
    g_csrc[pos] = ei[e];
}

// warp-per-dst gather: agg[d] = (1/deg) * sum h[src]
__global__ void gather_kernel(const float* __restrict__ h, float* __restrict__ agg, int b) {
    int w = blockIdx.x * (blockDim.x >> 5) + (threadIdx.x >> 5);
    if (w >= NN) return;
    int lane = threadIdx.x & 31;
    int seg = b * NN + w;
    int lo = g_coff[seg];
    int deg = g_icnt[seg];
    float4 acc = make_float4(0.f, 0.f, 0.f, 0.f);
    const float4* h4 = reinterpret_cast<const float4*>(h);
    for (int j0 = 0; j0 < deg; j0 += 32) {
        int rem = deg - j0;
        int m = rem < 32 ? rem : 32;
        int idx = (lane < m) ? g_csrc[lo + j0 + lane] : 0;
        for (int j = 0; j < m; ++j) {
            int s = __shfl_sync(0xFFFFFFFFu, idx, j);
            float4 v = h4[(size_t)s * 32 + lane];
            acc.x += v.x; acc.y += v.y; acc.z += v.z; acc.w += v.w;
        }
    }
    float r = g_rd[seg];
    acc.x *= r; acc.y *= r; acc.z *= r; acc.w *= r;
    reinterpret_cast<float4*>(agg)[(size_t)w * 32 + lane] = acc;
}

// ---------------- weight -> bf16 hi/lo image (plain [k*128+n] layout) ----------------
__global__ void convert_w_kernel(const float* __restrict__ W, __nv_bfloat16* __restrict__ img) {
    int i = blockIdx.x * blockDim.x + threadIdx.x;
    if (i >= 16384) return;
    float v = W[i];
    __nv_bfloat16 h = __float2bfloat16(v);
    float r = v - __bfloat162float(h);
    img[i] = h;
    img[16384 + i] = __float2bfloat16(r);
}

// ---------------- split-bf16 tensor-core GEMM (ldmatrix + mma.sync) ----------------
// C[M,128] = A@W (+ A2@W2) + bias, optional relu; fused BN colstat / Q-dot logits.
// CTA = 128 rows, 256 threads = 8 warps in 4x2 (warp: 32 rows x 64 cols).
// Split: Ah*Wh + Ah*Wl + Al*Wh, fp32 accumulate in registers.
constexpr int TS_STRIDE_B = 272;                    // 136 bf16 per smem row
constexpr int TILE_BYTES = 128 * TS_STRIDE_B;       // 34816
constexpr int OFF_AH = 0;
constexpr int OFF_AL = TILE_BYTES;
constexpr int OFF_WH = 2 * TILE_BYTES;
constexpr int OFF_WL = 3 * TILE_BYTES;
constexpr int OFF_RED = 4 * TILE_BYTES;             // 139264: sd[128] + sc[512]
constexpr int TSG_SMEM = OFF_RED + 640 * 4;         // 141824
constexpr int STAGE_STRIDE = 132;                   // fp32 stage, reuses tile smem

__global__ __launch_bounds__(256) void tsgemm_kernel(
    const float* __restrict__ A, const __nv_bfloat16* __restrict__ Wimg,
    const float* __restrict__ A2, const __nv_bfloat16* __restrict__ W2img,
    const float* __restrict__ bias, float* __restrict__ C,
    int M, int relu, int do_colstat,
    const float* __restrict__ Qdot, float* __restrict__ logits, int bidx)
{
    extern __shared__ char smem[];
    uint32_t sb = smem_to_u32(smem);
    int tid = threadIdx.x;
    int w = tid >> 5, lane = tid & 31;
    int wr = w & 3, wc = w >> 2;
    int g = lane >> 2, t4 = lane & 3;
    int row0 = blockIdx.x * 128;

    float acc[2][8][4];
#pragma unroll
    for (int mi = 0; mi < 2; mi++)
#pragma unroll
        for (int ni = 0; ni < 8; ni++)
#pragma unroll
            for (int c = 0; c < 4; c++) acc[mi][ni][c] = 0.f;

    // lane-invariant ldmatrix address pieces
    int l_row8 = ((lane >> 3) & 1) * 8 + (lane & 7);   // row within 16
    int l_col8 = (lane >> 4) * 8;                      // 0 or 8

    for (int pass = 0; pass < 2; ++pass) {
        const float* Ap = pass ? A2 : A;
        const __nv_bfloat16* Wp = pass ? W2img : Wimg;
        if (Ap == nullptr) break;
        if (pass) __syncthreads();       // all reads of previous tiles done

        // copy W hi+lo images into padded smem rows (17 uint4 per 128-col row)
        {
            const uint4* srch = reinterpret_cast<const uint4*>(Wp);
            const uint4* srcl = srch + 2048;
#pragma unroll
            for (int i = 0; i < 8; ++i) {
                int idx = tid + i * 256;
                int row = idx >> 4, seg = idx & 15;
                *reinterpret_cast<uint4*>(smem + OFF_WH + row * TS_STRIDE_B + seg * 16) = srch[idx];
                *reinterpret_cast<uint4*>(smem + OFF_WL + row * TS_STRIDE_B + seg * 16) = srcl[idx];
            }
        }
        // load + split-convert A tile (fp32 -> bf16 hi/lo)
#pragma unroll
        for (int i = 0; i < 16; ++i) {
            int idx = tid + i * 256;
            int r = idx >> 5, c4 = idx & 31;
            float4 a = make_float4(0.f, 0.f, 0.f, 0.f);
            if (row0 + r < M) a = reinterpret_cast<const float4*>(Ap)[(size_t)(row0 + r) * 32 + c4];
            unsigned h0, h1, l0v, l1v;
            asm("cvt.rn.bf16x2.f32 %0, %1, %2;" : "=r"(h0) : "f"(a.y), "f"(a.x));
            asm("cvt.rn.bf16x2.f32 %0, %1, %2;" : "=r"(h1) : "f"(a.w), "f"(a.z));
            float rx = a.x - __uint_as_float(h0 << 16);
            float ry = a.y - __uint_as_float(h0 & 0xFFFF0000u);
            float rz = a.z - __uint_as_float(h1 << 16);
            float rw = a.w - __uint_as_float(h1 & 0xFFFF0000u);
            asm("cvt.rn.bf16x2.f32 %0, %1, %2;" : "=r"(l0v) : "f"(ry), "f"(rx));
            asm("cvt.rn.bf16x2.f32 %0, %1, %2;" : "=r"(l1v) : "f"(rw), "f"(rz));
            int off = r * TS_STRIDE_B + c4 * 8;
            *reinterpret_cast<uint2*>(smem + OFF_AH + off) = make_uint2(h0, h1);
            *reinterpret_cast<uint2*>(smem + OFF_AL + off) = make_uint2(l0v, l1v);
        }
        __syncthreads();

        // 3 split sub-passes: (Ah,Wh), (Ah,Wl), (Al,Wh)
#pragma unroll
        for (int sp = 0; sp < 3; ++sp) {
            uint32_t Ab = sb + (sp == 2 ? OFF_AL : OFF_AH);
            uint32_t Wb = sb + (sp == 1 ? OFF_WL : OFF_WH);
#pragma unroll
            for (int ks = 0; ks < 8; ++ks) {
                uint32_t af[2][4];
#pragma unroll
                for (int mi = 0; mi < 2; ++mi) {
                    int arow = wr * 32 + mi * 16 + l_row8;
                    int acol = ks * 16 + l_col8;
                    LDSM_X4(af[mi][0], af[mi][1], af[mi][2], af[mi][3],
                            Ab + arow * TS_STRIDE_B + acol * 2);
                }
                uint32_t bf[8][2];
#pragma unroll
                for (int nb = 0; nb < 4; ++nb) {
                    int krow = ks * 16 + l_row8;
                    int ncol = wc * 64 + nb * 16 + l_col8;
                    uint32_t r0, r1, r2, r3;
                    LDSM_X4_T(r0, r1, r2, r3, Wb + krow * TS_STRIDE_B + ncol * 2);
                    bf[nb * 2][0] = r0; bf[nb * 2][1] = r1;
                    bf[nb * 2 + 1][0] = r2; bf[nb * 2 + 1][1] = r3;
                }
#pragma unroll
                for (int mi = 0; mi < 2; ++mi)
#pragma unroll
                    for (int ni = 0; ni < 8; ++ni)
                        MMA_BF16(acc[mi][ni], af[mi], bf[ni]);
            }
        }
    }
    __syncthreads();    // tiles no longer needed; reuse as fp32 stage

    // stage accumulators: stage[128][132]
    float* stage = reinterpret_cast<float*>(smem);
    float* sd = reinterpret_cast<float*>(smem + OFF_RED);     // 128 floats
    float* sc = sd + 128;                                     // 512 floats
#pragma unroll
    for (int mi = 0; mi < 2; ++mi)
#pragma unroll
        for (int ni = 0; ni < 8; ++ni) {
            int row = wr * 32 + mi * 16 + g;
            int col = wc * 64 + ni * 8 + 2 * t4;
            *reinterpret_cast<float2*>(&stage[row * STAGE_STRIDE + col]) =
                make_float2(acc[mi][ni][0], acc[mi][ni][1]);
            *reinterpret_cast<float2*>(&stage[(row + 8) * STAGE_STRIDE + col]) =
                make_float2(acc[mi][ni][2], acc[mi][ni][3]);
        }
    if (Qdot && tid < 128) sd[tid] = 0.f;
    __syncthreads();

    float s = 0.f, q = 0.f;
    for (int i = tid; i < 16384; i += 256) {
        int r = i >> 7, c = i & 127;
        float v = stage[r * STAGE_STRIDE + c];
        if (bias) v += bias[c];
        if (relu) v = fmaxf(v, 0.f);
        bool valid = (row0 + r) < M;
        if (C != nullptr && valid) C[(size_t)(row0 + r) * 128 + c] = v;
        if (do_colstat && valid) { s += v; q += v * v; }
        if (Qdot != nullptr) {
            float pp = valid ? v * Qdot[(size_t)(row0 + r) * 128 + c] : 0.f;
#pragma unroll
            for (int o = 16; o; o >>= 1) pp += __shfl_xor_sync(0xFFFFFFFFu, pp, o);
            if (lane == 0) atomicAdd(&sd[r], pp);
        }
    }
    if (do_colstat) {
        sc[tid] = s; sc[256 + tid] = q;
        __syncthreads();
        if (tid < 128) {
            atomicAdd(&g_colstat[tid], sc[tid] + sc[tid + 128]);
            atomicAdd(&g_colstat[128 + tid], sc[256 + tid] + sc[256 + tid + 128]);
        }
    }
    if (Qdot != nullptr) {
        __syncthreads();
        if (tid < 128 && row0 + tid < M)
            logits[(size_t)(row0 + tid) * BB + bidx] = sd[tid];
    }
}

// ---------------- BatchNorm finalize / apply ----------------
__global__ void bn_finalize_kernel(const float* __restrict__ gamma, const float* __restrict__ beta) {
    int c = threadIdx.x;
    if (c >= DD) return;
    float mu = g_colstat[c] * (1.0f / NN);
    float var = g_colstat[DD + c] * (1.0f / NN) - mu * mu;
    float sc = gamma[c] * rsqrtf(var + BN_EPS);
    g_bnsc[c] = sc;
    g_bnsh[c] = beta[c] - mu * sc;
}

__global__ void bn_apply_kernel(float* __restrict__ h, const float* __restrict__ x,
                                float* __restrict__ outstack, int mode) {
    int idx = blockIdx.x * blockDim.x + threadIdx.x;
    if (idx >= NN * 32) return;
    int c4 = (idx & 31) * 4;
    float4 v = reinterpret_cast<float4*>(h)[idx];
    float4 o;
    o.x = v.x * g_bnsc[c4 + 0] + g_bnsh[c4 + 0];
    o.y = v.y * g_bnsc[c4 + 1] + g_bnsh[c4 + 1];
    o.z = v.z * g_bnsc[c4 + 2] + g_bnsh[c4 + 2];
    o.w = v.w * g_bnsc[c4 + 3] + g_bnsh[c4 + 3];
    if (mode == 0) {
        o.x = fmaxf(o.x, 0.f); o.y = fmaxf(o.y, 0.f);
        o.z = fmaxf(o.z, 0.f); o.w = fmaxf(o.w, 0.f);
        reinterpret_cast<float4*>(h)[idx] = o;
    } else {
        float4 xv = reinterpret_cast<const float4*>(x)[idx];
        o.x += xv.x; o.y += xv.y; o.z += xv.z; o.w += xv.w;
        reinterpret_cast<float4*>(outstack)[idx] = o;
    }
}

// ---------------- softmax + weighted fuse ----------------
__global__ void softmax_fuse_kernel(const float* __restrict__ logits,
                                    const float* __restrict__ stack,
                                    float* __restrict__ out) {
    int idx = blockIdx.x * blockDim.x + threadIdx.x;
    if (idx >= NN * 32) return;
    int n = idx >> 5;
    float l0 = logits[(size_t)n * 3 + 0];
    float l1 = logits[(size_t)n * 3 + 1];
    float l2 = logits[(size_t)n * 3 + 2];
    float m = fmaxf(l0, fmaxf(l1, l2));
    float e0 = __expf(l0 - m), e1 = __expf(l1 - m), e2 = __expf(l2 - m);
    float inv = 1.0f / (e0 + e1 + e2);
    float w0 = e0 * inv, w1 = e1 * inv, w2 = e2 * inv;
    float4 s0 = reinterpret_cast<const float4*>(stack)[idx];
    float4 s1 = reinterpret_cast<const float4*>(stack + (size_t)NN * DD)[idx];
    float4 s2 = reinterpret_cast<const float4*>(stack + (size_t)2 * NN * DD)[idx];
    float4 o;
    o.x = w0 * s0.x + w1 * s1.x + w2 * s2.x;
    o.y = w0 * s0.y + w1 * s1.y + w2 * s2.y;
    o.z = w0 * s0.z + w1 * s1.z + w2 * s2.z;
    o.w = w0 * s0.w + w1 * s1.w + w2 * s2.w;
    reinterpret_cast<float4*>(out)[idx] = o;
}

__global__ void bias_combine_kernel(const float* __restrict__ fuse_b,
                                    const float* __restrict__ refine_W,
                                    const float* __restrict__ refine_b) {
    int c = threadIdx.x;
    if (c >= DD) return;
    float s = refine_b[c];
    for (int k = 0; k < DD; ++k) s += fuse_b[k] * refine_W[k * DD + c];
    g_bc[c] = s;
}

// ---------------- host launch ----------------
static inline int gblk(int m) { return (m + 127) / 128; }

extern "C" void kernel_launch(void* const* d_in, const int* in_sizes, int n_in,
                              void* d_out, int out_size) {
    const int*   ei          = (const int*)d_in[0];
    const int*   et          = (const int*)d_in[1];
    const float* item_feats  = (const float*)d_in[2];
    const float* user_emb    = (const float*)d_in[3];
    const float* user_proj_W = (const float*)d_in[4];
    const float* user_proj_b = (const float*)d_in[5];
    const float* item_proj_W = (const float*)d_in[6];
    const float* item_proj_b = (const float*)d_in[7];
    const float* sage_Wl     = (const float*)d_in[8];
    const float* sage_bl     = (const float*)d_in[9];
    const float* sage_Wr     = (const float*)d_in[10];
    const float* bn_gamma    = (const float*)d_in[11];
    const float* bn_beta     = (const float*)d_in[12];
    const float* query_W     = (const float*)d_in[13];
    const float* query_b     = (const float*)d_in[14];
    const float* key_W       = (const float*)d_in[15];
    const float* key_b       = (const float*)d_in[16];
    const float* fuse_W      = (const float*)d_in[17];
    const float* fuse_b      = (const float*)d_in[18];
    const float* refine_W    = (const float*)d_in[19];
    const float* refine_b    = (const float*)d_in[20];
    float* out = (float*)d_out;
    (void)in_sizes; (void)n_in; (void)out_size;

    float *px, *ph, *pagg, *pQ, *pstack, *plog, *pWc, *pbc;
    int* picnt;
    __nv_bfloat16* pimg;
    cudaGetSymbolAddress((void**)&px,     g_x);
    cudaGetSymbolAddress((void**)&ph,     g_h);
    cudaGetSymbolAddress((void**)&pagg,   g_agg);
    cudaGetSymbolAddress((void**)&pQ,     g_Q);
    cudaGetSymbolAddress((void**)&pstack, g_stack);
    cudaGetSymbolAddress((void**)&plog,   g_logits);
    cudaGetSymbolAddress((void**)&pWc,    g_Wc);
    cudaGetSymbolAddress((void**)&pbc,    g_bc);
    cudaGetSymbolAddress((void**)&picnt,  g_icnt);
    cudaGetSymbolAddress((void**)&pimg,   g_wimg);

    cudaFuncSetAttribute(tsgemm_kernel, cudaFuncAttributeMaxDynamicSharedMemorySize, TSG_SMEM);

    const int NV4 = NN * 32;
    const int APPLY_GRID = (NV4 + 255) / 256;
    const int GATHER_GRID = (NN + 7) / 8;
    const int GB = gblk(NN);                      // 1172

    auto img = [&](int slot) { return pimg + (size_t)slot * 2 * 16384; };
    // slots: 0 user_proj, 1 item_proj, 2+bl Wl, 8+bl Wr, 14 query, 15+b key, 18 refine, 19 Wc

    // ---- edge preprocessing: CSR by (behavior, dst) ----
    zero_int_kernel<<<256, 256>>>((int4*)picnt, SEGS / 4);
    count_kernel<<<(EE + 255) / 256, 256>>>(ei, et);
    scan1_kernel<<<SCAN_BLOCKS, 1024>>>();
    scan2_kernel<<<1, 512>>>();
    scan3_kernel<<<SCAN_BLOCKS, 1024>>>();
    fill_kernel<<<(EE + 255) / 256, 256>>>(ei, et);

    // ---- weight image conversions ----
    convert_w_kernel<<<64, 256>>>(user_proj_W, img(0));
    convert_w_kernel<<<64, 256>>>(item_proj_W, img(1));
    for (int bl = 0; bl < 6; ++bl) {
        convert_w_kernel<<<64, 256>>>(sage_Wl + (size_t)bl * DD * DD, img(2 + bl));
        convert_w_kernel<<<64, 256>>>(sage_Wr + (size_t)bl * DD * DD, img(8 + bl));
    }
    convert_w_kernel<<<64, 256>>>(query_W, img(14));
    for (int b = 0; b < BB; ++b)
        convert_w_kernel<<<64, 256>>>(key_W + (size_t)b * DD * DD, img(15 + b));
    convert_w_kernel<<<64, 256>>>(refine_W, img(18));

    // Wc = fuse_W @ refine_W, then its image; combined bias
    tsgemm_kernel<<<1, 256, TSG_SMEM>>>(fuse_W, img(18), nullptr, nullptr,
        nullptr, pWc, DD, 0, 0, nullptr, nullptr, 0);
    convert_w_kernel<<<64, 256>>>(pWc, img(19));
    bias_combine_kernel<<<1, 128>>>(fuse_b, refine_W, refine_b);

    // initial features
    tsgemm_kernel<<<gblk(NUSER), 256, TSG_SMEM>>>(user_emb, img(0), nullptr, nullptr,
        user_proj_b, px, NUSER, 0, 0, nullptr, nullptr, 0);
    tsgemm_kernel<<<gblk(NITEM), 256, TSG_SMEM>>>(item_feats, img(1), nullptr, nullptr,
        item_proj_b, px + (size_t)NUSER * DD, NITEM, 0, 0, nullptr, nullptr, 0);

    for (int b = 0; b < BB; ++b) {
        const float* hin = px;
        for (int l = 0; l < LL; ++l) {
            int bl = b * LL + l;
            gather_kernel<<<GATHER_GRID, 256>>>(hin, pagg, b);
            zero_stats_kernel<<<1, 256>>>();
            tsgemm_kernel<<<GB, 256, TSG_SMEM>>>(pagg, img(2 + bl), hin, img(8 + bl),
                sage_bl + (size_t)bl * DD, ph, NN, 0, 1, nullptr, nullptr, 0);
            bn_finalize_kernel<<<1, 128>>>(bn_gamma + (size_t)bl * DD, bn_beta + (size_t)bl * DD);
            if (l < LL - 1) {
                bn_apply_kernel<<<APPLY_GRID, 256>>>(ph, px, nullptr, 0);
            } else {
                bn_apply_kernel<<<APPLY_GRID, 256>>>(ph, px,
                    pstack + (size_t)b * NN * DD, 1);
            }
            hin = ph;
        }
    }

    // attention: Q, then K-GEMMs with fused Q-dot
    tsgemm_kernel<<<GB, 256, TSG_SMEM>>>(px, img(14), nullptr, nullptr,
        query_b, pQ, NN, 0, 0, nullptr, nullptr, 0);
    for (int b = 0; b < BB; ++b) {
        tsgemm_kernel<<<GB, 256, TSG_SMEM>>>(pstack + (size_t)b * NN * DD, img(15 + b),
            nullptr, nullptr, key_b + (size_t)b * DD, nullptr, NN, 0, 0, pQ, plog, b);
    }
    softmax_fuse_kernel<<<APPLY_GRID, 256>>>(plog, pstack, ph);

    // final: relu(Fused @ Wc + bc)
    tsgemm_kernel<<<GB, 256, TSG_SMEM>>>(ph, img(19), nullptr, nullptr,
        pbc, out, NN, 1, 0, nullptr, nullptr, 0);
}